// round 5
// baseline (speedup 1.0000x reference)
#include <cuda_runtime.h>
#include <cstdint>
#include <cstddef>

#define NB 512
#define NN 1000
#define DD 128

using u64 = unsigned long long;

__device__ __forceinline__ u64 pack2(float lo, float hi) {
    u64 r; asm("mov.b64 %0, {%1, %2};" : "=l"(r) : "f"(lo), "f"(hi)); return r;
}
__device__ __forceinline__ void unpack2(u64 v, float& lo, float& hi) {
    asm("mov.b64 {%0, %1}, %2;" : "=f"(lo), "=f"(hi) : "l"(v));
}
__device__ __forceinline__ u64 ffma2(u64 a, u64 b, u64 c) {
    u64 d; asm("fma.rn.f32x2 %0, %1, %2, %3;" : "=l"(d) : "l"(a), "l"(b), "l"(c)); return d;
}

__global__ __launch_bounds__(256, 2)
void fused_ptr_attn_kernel(const float* __restrict__ state,   // [B,384]
                           const float* __restrict__ ctx,     // [B,N,128]
                           const int*   __restrict__ mask,    // [B,N]
                           const float* __restrict__ Wq,      // [384,128]
                           const float* __restrict__ Wkm,     // [128,128]
                           const float* __restrict__ Wv,      // [128,128]
                           const float* __restrict__ Wfc,     // [128,128]
                           const float* __restrict__ Wk,      // [128,128]
                           const int*   __restrict__ Tp,
                           float* __restrict__ out)           // [B,N]
{
    // Every array that is ever accessed through a float4* MUST be 16B-aligned:
    // shared float[] only guarantees 4B alignment (this caused the R3 trap).
    __shared__ __align__(16) float s_state[384];
    __shared__ __align__(16) float s_q[128];
    __shared__ __align__(16) float s_Qt[8][128];     // per-head projected query (0.25 folded)
    __shared__ __align__(16) float s_sun[4][8][128]; // per-warp-pair weighted context sums
    __shared__ __align__(16) float s_x128[2][128];
    __shared__ __align__(16) float s_xfc[2][128];
    __shared__ __align__(16) float s_y[128];
    __shared__ __align__(16) float s_p[NN];
    __shared__ short s_idx[NN];                      // compacted unmasked row ids
    __shared__ int   s_cnt;
    __shared__ float s_den[8][8];                    // [warp][h]
    __shared__ float s_denf[8];
    __shared__ float s_den2[8];
    __shared__ float s_inv;
    __shared__ int   s_mask[NN];

    const int t    = threadIdx.x;
    const int w    = t >> 5;
    const int lane = t & 31;
    const int b    = blockIdx.x;
    const float* ctxb = ctx + (size_t)b * NN * DD;

    // ---------------- prologue loads ----------------
    if (t < 128) {
        s_state[t]       = state[(size_t)b * 384 + t];
        s_state[t + 128] = state[(size_t)b * 384 + 128 + t];
        s_state[t + 256] = state[(size_t)b * 384 + 256 + t];
    }
    for (int i = t; i < NN; i += 256) {
        s_mask[i] = mask[(size_t)b * NN + i];
        s_p[i] = 0.f;
    }
    __syncthreads();

    // warp 0: compact unmasked indices; threads 128..255: q = state @ Wq
    if (w == 0) {
        int base = 0;
        for (int i0 = 0; i0 < NN; i0 += 32) {
            int n = i0 + lane;
            int m = (n < NN) ? s_mask[n] : 1;
            unsigned bal = __ballot_sync(0xffffffffu, m == 0);
            if (m == 0) {
                int pre = __popc(bal & ((1u << lane) - 1u));
                s_idx[base + pre] = (short)n;
            }
            base += __popc(bal);
        }
        if (lane == 0) s_cnt = base;
    } else if (t >= 128) {
        int col = t - 128;
        float a0 = 0.f, a1 = 0.f, a2 = 0.f, a3 = 0.f;
        #pragma unroll 4
        for (int i = 0; i < 384; i += 4) {
            a0 = fmaf(s_state[i    ], __ldg(&Wq[(i    ) * 128 + col]), a0);
            a1 = fmaf(s_state[i + 1], __ldg(&Wq[(i + 1) * 128 + col]), a1);
            a2 = fmaf(s_state[i + 2], __ldg(&Wq[(i + 2) * 128 + col]), a2);
            a3 = fmaf(s_state[i + 3], __ldg(&Wq[(i + 3) * 128 + col]), a3);
        }
        s_q[col] = (a0 + a1) + (a2 + a3);
    }
    __syncthreads();

    // ---------------- Qt[h][d] = 0.25 * sum_j Wkm[d][16h+j] * q[16h+j] ----------------
    {
        const int hw    = w & 3;          // hid chunk of 32
        const int dbase = (w >> 2) * 64;  // d half
        const int hid   = hw * 32 + lane;
        const float ql  = s_q[hid];
        const int head0 = hw * 2 + (lane >> 4);
        #pragma unroll 4
        for (int dd = 0; dd < 64; dd++) {
            int d = dbase + dd;
            float p = __ldg(&Wkm[d * 128 + hid]) * ql;
            p += __shfl_xor_sync(0xffffffffu, p, 8);
            p += __shfl_xor_sync(0xffffffffu, p, 4);
            p += __shfl_xor_sync(0xffffffffu, p, 2);
            p += __shfl_xor_sync(0xffffffffu, p, 1);
            if ((lane & 15) == 0) s_Qt[head0][d] = 0.25f * p;
        }
    }
    __syncthreads();

    // ---------------- pass 1: stream unmasked rows ----------------
    u64 qt2[8][2];
    u64 acc2[8][2];
    #pragma unroll
    for (int h = 0; h < 8; h++) {
        float4 qv = *reinterpret_cast<const float4*>(&s_Qt[h][lane * 4]);
        qt2[h][0] = pack2(qv.x, qv.y);
        qt2[h][1] = pack2(qv.z, qv.w);
        acc2[h][0] = 0ull;
        acc2[h][1] = 0ull;
    }
    float denl = 0.f;
    const int cnt = s_cnt;

    auto row1 = [&](float4 c, bool valid) {
        u64 cA = pack2(c.x, c.y), cB = pack2(c.z, c.w);
        float p[8];
        #pragma unroll
        for (int h = 0; h < 8; h++) {
            u64 s = ffma2(cA, qt2[h][0], ffma2(cB, qt2[h][1], 0ull));
            float lo, hi; unpack2(s, lo, hi);
            p[h] = lo + hi;
        }
        // multi-value halving reduction: 8 dots over 32 lanes in 9 shfls
        #pragma unroll
        for (int i = 0; i < 4; i++) {
            float send = (lane & 16) ? p[i] : p[i + 4];
            float keep = (lane & 16) ? p[i + 4] : p[i];
            p[i] = keep + __shfl_xor_sync(0xffffffffu, send, 16);
        }
        #pragma unroll
        for (int i = 0; i < 2; i++) {
            float send = (lane & 8) ? p[i] : p[i + 2];
            float keep = (lane & 8) ? p[i + 2] : p[i];
            p[i] = keep + __shfl_xor_sync(0xffffffffu, send, 8);
        }
        {
            float send = (lane & 4) ? p[0] : p[1];
            float keep = (lane & 4) ? p[1] : p[0];
            p[0] = keep + __shfl_xor_sync(0xffffffffu, send, 4);
        }
        p[0] += __shfl_xor_sync(0xffffffffu, p[0], 2);
        p[0] += __shfl_xor_sync(0xffffffffu, p[0], 1);
        // lane holds full dot for head h(lane) = (lane>>2)&7 (bit4*4+bit3*2+bit2)
        float e = valid ? __expf(p[0]) : 0.f;
        denl += e;
        float eh[8];
        #pragma unroll
        for (int h = 0; h < 8; h++) eh[h] = __shfl_sync(0xffffffffu, e, h * 4);
        #pragma unroll
        for (int h = 0; h < 8; h++) {
            u64 e2 = pack2(eh[h], eh[h]);
            acc2[h][0] = ffma2(e2, cA, acc2[h][0]);
            acc2[h][1] = ffma2(e2, cB, acc2[h][1]);
        }
    };

    const float4* ctx4 = reinterpret_cast<const float4*>(ctxb);
    for (int j = w; j < cnt; j += 32) {
        bool v1 = (j + 8) < cnt, v2 = (j + 16) < cnt, v3 = (j + 24) < cnt;
        int n0 = s_idx[j];
        int n1 = v1 ? s_idx[j + 8]  : n0;
        int n2 = v2 ? s_idx[j + 16] : n0;
        int n3 = v3 ? s_idx[j + 24] : n0;
        float4 c0 = __ldg(ctx4 + n0 * 32 + lane);
        float4 c1 = __ldg(ctx4 + n1 * 32 + lane);
        float4 c2 = __ldg(ctx4 + n2 * 32 + lane);
        float4 c3 = __ldg(ctx4 + n3 * 32 + lane);
        row1(c0, true);
        row1(c1, v1);
        row1(c2, v2);
        row1(c3, v3);
    }

    // combine per-warp accumulators deterministically (2 stages, 4 slices)
    __syncthreads();
    if (w < 4) {
        #pragma unroll
        for (int h = 0; h < 8; h++) {
            float x0, x1, x2, x3;
            unpack2(acc2[h][0], x0, x1); unpack2(acc2[h][1], x2, x3);
            *reinterpret_cast<float4*>(&s_sun[w][h][lane * 4]) = make_float4(x0, x1, x2, x3);
        }
    }
    if ((lane & 3) == 0) s_den[w][lane >> 2] = denl;
    __syncthreads();
    if (w >= 4) {
        #pragma unroll
        for (int h = 0; h < 8; h++) {
            float x0, x1, x2, x3;
            unpack2(acc2[h][0], x0, x1); unpack2(acc2[h][1], x2, x3);
            float4* q4 = reinterpret_cast<float4*>(&s_sun[w - 4][h][lane * 4]);
            float4 o = *q4;
            *q4 = make_float4(o.x + x0, o.y + x1, o.z + x2, o.w + x3);
        }
    }
    __syncthreads();
    for (int k = t; k < 1024; k += 256) {
        int h = k >> 7, d = k & 127;
        s_sun[0][h][d] = (s_sun[0][h][d] + s_sun[1][h][d]) + (s_sun[2][h][d] + s_sun[3][h][d]);
    }
    if (t < 8) {
        float s = 0.f;
        #pragma unroll
        for (int ww = 0; ww < 8; ww++) s += s_den[ww][t];
        s_denf[t] = s;
    }
    __syncthreads();

    // ---------------- x128[hid] = (sum_d s_un[h][d] * Wv[d][hid]) / den[h] ----------------
    {
        int col = t & 127, half = t >> 7, h = col >> 4;
        int db = half * 64;
        float a0 = 0.f, a1 = 0.f;
        #pragma unroll 8
        for (int d = 0; d < 64; d += 2) {
            a0 = fmaf(s_sun[0][h][db + d],     __ldg(&Wv[(db + d)     * 128 + col]), a0);
            a1 = fmaf(s_sun[0][h][db + d + 1], __ldg(&Wv[(db + d + 1) * 128 + col]), a1);
        }
        s_x128[half][col] = a0 + a1;
    }
    __syncthreads();
    if (t < 128) s_x128[0][t] = (s_x128[0][t] + s_x128[1][t]) / s_denf[t >> 4];
    __syncthreads();

    // ---------------- xfc = x128 @ Wfc ----------------
    {
        int col = t & 127, half = t >> 7;
        int hb = half * 64;
        float a0 = 0.f, a1 = 0.f;
        #pragma unroll 8
        for (int i = 0; i < 64; i += 2) {
            a0 = fmaf(s_x128[0][hb + i],     __ldg(&Wfc[(hb + i)     * 128 + col]), a0);
            a1 = fmaf(s_x128[0][hb + i + 1], __ldg(&Wfc[(hb + i + 1) * 128 + col]), a1);
        }
        s_xfc[half][col] = a0 + a1;
    }
    __syncthreads();
    if (t < 128) s_xfc[0][t] = s_xfc[0][t] + s_xfc[1][t];
    __syncthreads();

    // ---------------- y[d] = norm_p * sum_hid Wk[d][hid] * xfc[hid] ----------------
    {
        const float nrm = 0.088388347648318447f;  // 1/sqrt(128)
        float4 xv = *reinterpret_cast<const float4*>(&s_xfc[0][lane * 4]);
        #pragma unroll 4
        for (int dd = 0; dd < 16; dd++) {
            int d = w * 16 + dd;
            float4 wv = __ldg(reinterpret_cast<const float4*>(&Wk[d * 128 + lane * 4]));
            float p = fmaf(wv.w, xv.w, fmaf(wv.z, xv.z, fmaf(wv.y, xv.y, wv.x * xv.x)));
            p += __shfl_xor_sync(0xffffffffu, p, 16);
            p += __shfl_xor_sync(0xffffffffu, p, 8);
            p += __shfl_xor_sync(0xffffffffu, p, 4);
            p += __shfl_xor_sync(0xffffffffu, p, 2);
            p += __shfl_xor_sync(0xffffffffu, p, 1);
            if (lane == 0) s_y[d] = p * nrm;
        }
    }
    __syncthreads();

    // ---------------- pass 2: pointer logits + softmax ----------------
    float Tf = 1.f;
    if (Tp) {
        unsigned r = *reinterpret_cast<const unsigned*>(Tp);
        float asf = __uint_as_float(r);
        Tf = (asf > 0.0078125f && asf < 1024.f) ? asf : (float)(int)r;
        if (!(Tf > 0.f)) Tf = 1.f;
    }
    const float invT = 1.0f / Tf;

    float4 yv = *reinterpret_cast<const float4*>(&s_y[lane * 4]);
    u64 y2a = pack2(yv.x, yv.y), y2b = pack2(yv.z, yv.w);
    float den2 = 0.f;

    auto row2 = [&](float4 c, int n, bool valid) {
        u64 cA = pack2(c.x, c.y), cB = pack2(c.z, c.w);
        u64 s = ffma2(cA, y2a, ffma2(cB, y2b, 0ull));
        float lo, hi; unpack2(s, lo, hi);
        float p = lo + hi;
        p += __shfl_xor_sync(0xffffffffu, p, 16);
        p += __shfl_xor_sync(0xffffffffu, p, 8);
        p += __shfl_xor_sync(0xffffffffu, p, 4);
        p += __shfl_xor_sync(0xffffffffu, p, 2);
        p += __shfl_xor_sync(0xffffffffu, p, 1);
        float tt = __expf(2.f * p);
        float th = 1.f - __fdividef(2.f, tt + 1.f);   // tanh, safe at +/-inf
        float pr = __expf(5.f * th * invT);
        if (valid && lane == 0) {
            s_p[n] = pr;
            den2 += pr;
        }
    };

    for (int j = w; j < cnt; j += 32) {
        bool v1 = (j + 8) < cnt, v2 = (j + 16) < cnt, v3 = (j + 24) < cnt;
        int n0 = s_idx[j];
        int n1 = v1 ? s_idx[j + 8]  : n0;
        int n2 = v2 ? s_idx[j + 16] : n0;
        int n3 = v3 ? s_idx[j + 24] : n0;
        float4 c0 = __ldg(ctx4 + n0 * 32 + lane);
        float4 c1 = __ldg(ctx4 + n1 * 32 + lane);
        float4 c2 = __ldg(ctx4 + n2 * 32 + lane);
        float4 c3 = __ldg(ctx4 + n3 * 32 + lane);
        row2(c0, n0, true);
        row2(c1, n1, v1);
        row2(c2, n2, v2);
        row2(c3, n3, v3);
    }
    if (lane == 0) s_den2[w] = den2;
    __syncthreads();
    if (t == 0) {
        float s = 0.f;
        #pragma unroll
        for (int ww = 0; ww < 8; ww++) s += s_den2[ww];
        s_inv = 1.0f / s;
    }
    __syncthreads();

    const float inv = s_inv;
    float* outb = out + (size_t)b * NN;
    for (int i = t; i < NN; i += 256) outb[i] = s_p[i] * inv;
}

extern "C" void kernel_launch(void* const* d_in, const int* in_sizes, int n_in,
                              void* d_out, int out_size) {
    (void)in_sizes; (void)out_size;
    const float* state = (const float*)d_in[0];
    const float* ctx   = (const float*)d_in[1];
    const int*   mask  = (const int*)d_in[2];
    const float* Wq    = (const float*)d_in[3];
    const float* Wkm   = (const float*)d_in[4];
    const float* Wv    = (const float*)d_in[5];
    const float* Wfc   = (const float*)d_in[6];
    const float* Wk    = (const float*)d_in[7];
    const int*   Tp    = (n_in > 8) ? (const int*)d_in[8] : nullptr;
    fused_ptr_attn_kernel<<<NB, 256>>>(state, ctx, mask, Wq, Wkm, Wv, Wfc, Wk, Tp,
                                       (float*)d_out);
}